// round 2
// baseline (speedup 1.0000x reference)
#include <cuda_runtime.h>
#include <math.h>

#define SEQ 50
#define DIM 32
#define NH  4
#define HDIM 8
#define NTHR 256
#define NWARP 8
#define FULLM 0xffffffffu

__global__ __launch_bounds__(NTHR, 4) void mha_fused_kernel(
    const float* __restrict__ Q, const float* __restrict__ K, const float* __restrict__ V,
    const float* __restrict__ ln_g, const float* __restrict__ ln_b,
    const float* __restrict__ Wq, const float* __restrict__ bq,
    const float* __restrict__ Wk, const float* __restrict__ bk,
    const float* __restrict__ Wv, const float* __restrict__ bv,
    const float* __restrict__ Wo, const float* __restrict__ bo,
    float* __restrict__ out)
{
    __shared__ __align__(16) float sq[SEQ * DIM];   // q proj, later ctx
    __shared__ __align__(16) float sk[SEQ * DIM];
    __shared__ __align__(16) float sv[SEQ * DIM];
    __shared__ float sWq[DIM * 33], sWk[DIM * 33], sWv[DIM * 33], sWo[DIM * 33];
    __shared__ float sbq[DIM], sbk[DIM], sbv[DIM], sbo[DIM], sg[DIM], sb[DIM];

    const int tid  = threadIdx.x;
    const int lane = tid & 31;
    const int wid  = tid >> 5;
    const size_t boff = (size_t)blockIdx.x * (SEQ * DIM);
    const float* Qb = Q + boff;
    const float* Kb = K + boff;
    const float* Vb = V + boff;

    // ---- load all weights/params once ----
    for (int i = tid; i < DIM * DIM; i += NTHR) {
        int j = i >> 5, d = i & 31;
        sWq[j * 33 + d] = Wq[i];
        sWk[j * 33 + d] = Wk[i];
        sWv[j * 33 + d] = Wv[i];
        sWo[j * 33 + d] = Wo[i];
    }
    if (tid < DIM) {
        sbq[tid] = bq[tid]; sbk[tid] = bk[tid];
        sbv[tid] = bv[tid]; sbo[tid] = bo[tid];
        sg[tid]  = ln_g[tid]; sb[tid] = ln_b[tid];
    }
    __syncthreads();

    // ---- fused LN + projection for Q,K,V: pool of 150 rows, warp per row ----
    for (int p = wid; p < 3 * SEQ; p += NWARP) {
        const int t = p / SEQ;            // 0=Q 1=K 2=V
        const int s = p - t * SEQ;
        const float* src  = (t == 0) ? Qb  : (t == 1) ? Kb  : Vb;
        const float* W    = (t == 0) ? sWq : (t == 1) ? sWk : sWv;
        const float* bias = (t == 0) ? sbq : (t == 1) ? sbk : sbv;
        float*       dst  = (t == 0) ? sq  : (t == 1) ? sk  : sv;

        float x = src[s * DIM + lane];
        float sum = x;
        #pragma unroll
        for (int o = 16; o; o >>= 1) sum += __shfl_xor_sync(FULLM, sum, o);
        float mu = sum * (1.0f / DIM);
        float dx = x - mu;
        float vs = dx * dx;
        #pragma unroll
        for (int o = 16; o; o >>= 1) vs += __shfl_xor_sync(FULLM, vs, o);
        float inv = rsqrtf(vs * (1.0f / DIM) + 1e-5f);
        float ln  = dx * inv * sg[lane] + sb[lane];

        float acc = bias[lane];
        const float* wr = W + lane * 33;
        #pragma unroll
        for (int d = 0; d < DIM; d++)
            acc = fmaf(__shfl_sync(FULLM, ln, d), wr[d], acc);
        dst[s * DIM + lane] = acc;
    }
    __syncthreads();

    // ---- attention: thread per (head, query row), two-pass causal softmax ----
    if (tid < NH * SEQ) {
        const int h = tid & 3;
        const int i = tid >> 2;
        const float* qrow = sq + i * DIM + h * HDIM;
        const float4 q0 = *(const float4*)qrow;
        const float4 q1 = *(const float4*)(qrow + 4);

        // pass 1: max over j <= i (max on raw dots; positive scale preserves order)
        float m = -1e30f;
        for (int j = 0; j <= i; j++) {
            const float* kr = sk + j * DIM + h * HDIM;
            float4 k0 = *(const float4*)kr;
            float4 k1 = *(const float4*)(kr + 4);
            float dot = q0.x*k0.x + q0.y*k0.y + q0.z*k0.z + q0.w*k0.w
                      + q1.x*k1.x + q1.y*k1.y + q1.z*k1.z + q1.w*k1.w;
            m = fmaxf(m, dot);
        }
        // pass 2: recompute dots, accumulate softmax-weighted V
        float ssum = 0.0f;
        float4 a0 = make_float4(0.f, 0.f, 0.f, 0.f);
        float4 a1 = make_float4(0.f, 0.f, 0.f, 0.f);
        const float scale = 0.35355339059327373f; // 1/sqrt(8)
        for (int j = 0; j <= i; j++) {
            const float* kr = sk + j * DIM + h * HDIM;
            float4 k0 = *(const float4*)kr;
            float4 k1 = *(const float4*)(kr + 4);
            float dot = q0.x*k0.x + q0.y*k0.y + q0.z*k0.z + q0.w*k0.w
                      + q1.x*k1.x + q1.y*k1.y + q1.z*k1.z + q1.w*k1.w;
            float w = __expf((dot - m) * scale);
            ssum += w;
            const float* vr = sv + j * DIM + h * HDIM;
            float4 v0 = *(const float4*)vr;
            float4 v1 = *(const float4*)(vr + 4);
            a0.x = fmaf(w, v0.x, a0.x); a0.y = fmaf(w, v0.y, a0.y);
            a0.z = fmaf(w, v0.z, a0.z); a0.w = fmaf(w, v0.w, a0.w);
            a1.x = fmaf(w, v1.x, a1.x); a1.y = fmaf(w, v1.y, a1.y);
            a1.z = fmaf(w, v1.z, a1.z); a1.w = fmaf(w, v1.w, a1.w);
        }
        float inv = 1.0f / ssum;
        a0.x *= inv; a0.y *= inv; a0.z *= inv; a0.w *= inv;
        a1.x *= inv; a1.y *= inv; a1.z *= inv; a1.w *= inv;
        // write ctx back into sq (this thread owns this 8-float segment)
        float* crow = sq + i * DIM + h * HDIM;
        *(float4*)crow = a0;
        *(float4*)(crow + 4) = a1;
    }
    __syncthreads();

    // ---- output projection + residual: warp per row ----
    float* ob = out + boff;
    for (int s = wid; s < SEQ; s += NWARP) {
        float acc = sbo[lane];
        const float* wr  = sWo + lane * 33;
        const float* ctx = sq + s * DIM;
        #pragma unroll
        for (int d = 0; d < DIM; d++)
            acc = fmaf(ctx[d], wr[d], acc);   // ctx[d] is a broadcast LDS
        ob[s * DIM + lane] = acc + Qb[s * DIM + lane];
    }
}

extern "C" void kernel_launch(void* const* d_in, const int* in_sizes, int n_in,
                              void* d_out, int out_size) {
    const float* Q    = (const float*)d_in[0];
    const float* K    = (const float*)d_in[1];
    const float* V    = (const float*)d_in[2];
    // d_in[3] = mask (static causal triu, implemented analytically)
    const float* ln_g = (const float*)d_in[4];
    const float* ln_b = (const float*)d_in[5];
    const float* Wq   = (const float*)d_in[6];
    const float* bq   = (const float*)d_in[7];
    const float* Wk   = (const float*)d_in[8];
    const float* bk   = (const float*)d_in[9];
    const float* Wv   = (const float*)d_in[10];
    const float* bv   = (const float*)d_in[11];
    const float* Wo   = (const float*)d_in[12];
    const float* bo   = (const float*)d_in[13];
    float* out = (float*)d_out;

    const int B = in_sizes[0] / (SEQ * DIM);  // 16384
    mha_fused_kernel<<<B, NTHR>>>(Q, K, V, ln_g, ln_b,
                                  Wq, bq, Wk, bk, Wv, bv, Wo, bo, out);
}

// round 3
// speedup vs baseline: 1.8589x; 1.8589x over previous
#include <cuda_runtime.h>
#include <math.h>

#define SEQ 50
#define DIM 32
#define NTHR 256
#define NWARP 8
#define FULLM 0xffffffffu
#define WPITCH 33

__global__ __launch_bounds__(NTHR, 4) void mha_fused_kernel(
    const float* __restrict__ Q, const float* __restrict__ K, const float* __restrict__ V,
    const float* __restrict__ ln_g, const float* __restrict__ ln_b,
    const float* __restrict__ Wq, const float* __restrict__ bq,
    const float* __restrict__ Wk, const float* __restrict__ bk,
    const float* __restrict__ Wv, const float* __restrict__ bv,
    const float* __restrict__ Wo, const float* __restrict__ bo,
    float* __restrict__ out)
{
    __shared__ __align__(16) float sbuf[3 * SEQ * DIM];   // raw rows -> projected (in place); q rows -> ctx
    __shared__ float sW[4 * DIM * WPITCH];                // Wq,Wk,Wv (get g-scaled), Wo raw; padded pitch 33
    __shared__ float2 sStats[3 * SEQ];                    // (mu, inv) per row
    __shared__ float sg[DIM], sb[DIM];
    __shared__ float sbias2[3 * DIM];                     // folded biases for q,k,v
    __shared__ float ssw[3 * DIM];                        // rowsum of g-scaled W for q,k,v
    __shared__ float sbo_[DIM];

    const int tid  = threadIdx.x;
    const int lane = tid & 31;
    const int wid  = tid >> 5;
    const size_t boff = (size_t)blockIdx.x * (SEQ * DIM);
    const float* Qb = Q + boff;
    const float* Kb = K + boff;
    const float* Vb = V + boff;

    // ---- stage weights (coalesced) into padded smem ----
    for (int i = tid; i < DIM * DIM; i += NTHR) {
        int r = i >> 5, c = i & 31;
        sW[0 * DIM * WPITCH + r * WPITCH + c] = Wq[i];
        sW[1 * DIM * WPITCH + r * WPITCH + c] = Wk[i];
        sW[2 * DIM * WPITCH + r * WPITCH + c] = Wv[i];
        sW[3 * DIM * WPITCH + r * WPITCH + c] = Wo[i];
    }
    if (tid < DIM) {
        sg[tid] = ln_g[tid]; sb[tid] = ln_b[tid];
        sbias2[tid] = bq[tid]; sbias2[DIM + tid] = bk[tid]; sbias2[2 * DIM + tid] = bv[tid];
        sbo_[tid] = bo[tid];
    }

    // ---- raw row loads + LN stats (Σx, Σx²), 4 rows per warp-iter ----
    {
        const int rsub = lane >> 3;   // row within 4-row block
        const int rk   = lane & 7;    // float4 segment within row
        for (int blk = wid; blk < (3 * SEQ + 3) / 4; blk += NWARP) {
            int gr = blk * 4 + rsub;
            float4 xv = make_float4(0.f, 0.f, 0.f, 0.f);
            if (gr < 3 * SEQ) {
                int t = gr / SEQ;
                int r = gr - t * SEQ;
                const float* src = (t == 0) ? Qb : (t == 1) ? Kb : Vb;
                xv = *(const float4*)(src + r * DIM + rk * 4);
                *(float4*)(sbuf + gr * DIM + rk * 4) = xv;
            }
            float s1 = xv.x + xv.y + xv.z + xv.w;
            float s2 = xv.x * xv.x + xv.y * xv.y + xv.z * xv.z + xv.w * xv.w;
            #pragma unroll
            for (int o = 4; o; o >>= 1) {
                s1 += __shfl_xor_sync(FULLM, s1, o);
                s2 += __shfl_xor_sync(FULLM, s2, o);
            }
            if (rk == 0 && gr < 3 * SEQ) {
                float mu  = s1 * (1.0f / DIM);
                float var = s2 * (1.0f / DIM) - mu * mu;
                sStats[gr] = make_float2(mu, rsqrtf(var + 1e-5f));
            }
        }
    }
    __syncthreads();

    // ---- fold LN params into q,k,v weights:
    //  bias2[j] += dot(b, Wrow);  sw[j] = dot(g, Wrow);  Wrow <- Wrow * g
    if (tid < 3 * DIM) {
        float* wr = sW + tid * WPITCH;
        float b2  = sbias2[tid];
        float swv = 0.f;
        #pragma unroll
        for (int d = 0; d < DIM; d++) {
            float w  = wr[d];
            float gw = w * sg[d];
            b2  = fmaf(w, sb[d], b2);
            swv += gw;
            wr[d] = gw;
        }
        sbias2[tid] = b2;
        ssw[tid]    = swv;
    }
    __syncthreads();

    // ---- projections: out[s][j] = inv_s*(dot(x_s, W'_j) - mu_s*sw_j) + bias2_j
    // 24 tasks = 3 tensors x 8 row-chunks; weights register-resident; in-place rows
    for (int task = wid; task < 24; task += NWARP) {
        const int t  = task >> 3;
        const int c  = task & 7;
        const int r0 = (c * SEQ) >> 3;
        const int r1 = ((c + 1) * SEQ) >> 3;       // chunks of 6-7 rows
        const float* wr = sW + (t * DIM + lane) * WPITCH;
        float wreg[DIM];
        #pragma unroll
        for (int d = 0; d < DIM; d++) wreg[d] = wr[d];
        const float b2  = sbias2[t * DIM + lane];
        const float swv = ssw[t * DIM + lane];
        float* base = sbuf + t * SEQ * DIM;

        float orow[7];
        const int nr = r1 - r0;
        #pragma unroll
        for (int r = 0; r < 7; r++) {
            if (r < nr) {
                const float4* xr = (const float4*)(base + (r0 + r) * DIM);
                float dot = 0.f;
                #pragma unroll
                for (int k2 = 0; k2 < 8; k2++) {
                    float4 xv = xr[k2];
                    dot = fmaf(xv.x, wreg[k2 * 4 + 0],
                          fmaf(xv.y, wreg[k2 * 4 + 1],
                          fmaf(xv.z, wreg[k2 * 4 + 2],
                          fmaf(xv.w, wreg[k2 * 4 + 3], dot))));
                }
                float2 st = sStats[t * SEQ + r0 + r];
                orow[r] = fmaf(st.y, fmaf(-st.x, swv, dot), b2);
            }
        }
        __syncwarp();   // all loads of this warp's rows done before overwrite
        #pragma unroll
        for (int r = 0; r < 7; r++)
            if (r < nr) base[(r0 + r) * DIM + lane] = orow[r];
    }
    __syncthreads();

    // ---- attention: thread per (head, query row); one-pass softmax (scores bounded) ----
    if (tid < 4 * SEQ) {
        const int h = tid & 3;
        const int i = tid >> 2;
        const float* sk_ = sbuf + SEQ * DIM;
        const float* sv_ = sbuf + 2 * SEQ * DIM;
        const float scale = 0.35355339059327373f;   // 1/sqrt(8)
        const float* qrow = sbuf + i * DIM + h * 8;
        float4 q0 = *(const float4*)qrow;
        float4 q1 = *(const float4*)(qrow + 4);
        q0.x *= scale; q0.y *= scale; q0.z *= scale; q0.w *= scale;
        q1.x *= scale; q1.y *= scale; q1.z *= scale; q1.w *= scale;

        float ssum = 0.f;
        float4 a0 = make_float4(0.f, 0.f, 0.f, 0.f);
        float4 a1 = make_float4(0.f, 0.f, 0.f, 0.f);
        for (int j = 0; j <= i; j++) {
            const float* kr = sk_ + j * DIM + h * 8;
            float4 k0 = *(const float4*)kr;
            float4 k1 = *(const float4*)(kr + 4);
            float dot = q0.x * k0.x + q0.y * k0.y + q0.z * k0.z + q0.w * k0.w
                      + q1.x * k1.x + q1.y * k1.y + q1.z * k1.z + q1.w * k1.w;
            float w = __expf(dot);
            ssum += w;
            const float* vr = sv_ + j * DIM + h * 8;
            float4 v0 = *(const float4*)vr;
            float4 v1 = *(const float4*)(vr + 4);
            a0.x = fmaf(w, v0.x, a0.x); a0.y = fmaf(w, v0.y, a0.y);
            a0.z = fmaf(w, v0.z, a0.z); a0.w = fmaf(w, v0.w, a0.w);
            a1.x = fmaf(w, v1.x, a1.x); a1.y = fmaf(w, v1.y, a1.y);
            a1.z = fmaf(w, v1.z, a1.z); a1.w = fmaf(w, v1.w, a1.w);
        }
        float inv = 1.0f / ssum;
        a0.x *= inv; a0.y *= inv; a0.z *= inv; a0.w *= inv;
        a1.x *= inv; a1.y *= inv; a1.z *= inv; a1.w *= inv;
        float* crow = sbuf + i * DIM + h * 8;   // ctx overwrites own q segment
        *(float4*)crow = a0;
        *(float4*)(crow + 4) = a1;
    }
    __syncthreads();

    // ---- output projection + residual (Wo register-resident; residual re-read from gmem) ----
    {
        const float* wr = sW + (3 * DIM + lane) * WPITCH;
        float wreg[DIM];
        #pragma unroll
        for (int d = 0; d < DIM; d++) wreg[d] = wr[d];
        const float b2 = sbo_[lane];
        float* ob = out + boff;
        const int r0 = (wid * SEQ) >> 3;
        const int r1 = ((wid + 1) * SEQ) >> 3;
        for (int r = r0; r < r1; r++) {
            const float4* xr = (const float4*)(sbuf + r * DIM);
            float dot = b2;
            #pragma unroll
            for (int k2 = 0; k2 < 8; k2++) {
                float4 xv = xr[k2];
                dot = fmaf(xv.x, wreg[k2 * 4 + 0],
                      fmaf(xv.y, wreg[k2 * 4 + 1],
                      fmaf(xv.z, wreg[k2 * 4 + 2],
                      fmaf(xv.w, wreg[k2 * 4 + 3], dot))));
            }
            ob[r * DIM + lane] = dot + Qb[r * DIM + lane];
        }
    }
}

extern "C" void kernel_launch(void* const* d_in, const int* in_sizes, int n_in,
                              void* d_out, int out_size) {
    const float* Q    = (const float*)d_in[0];
    const float* K    = (const float*)d_in[1];
    const float* V    = (const float*)d_in[2];
    // d_in[3] = mask (static causal triu, implemented analytically)
    const float* ln_g = (const float*)d_in[4];
    const float* ln_b = (const float*)d_in[5];
    const float* Wq   = (const float*)d_in[6];
    const float* bq   = (const float*)d_in[7];
    const float* Wk   = (const float*)d_in[8];
    const float* bk   = (const float*)d_in[9];
    const float* Wv   = (const float*)d_in[10];
    const float* bv   = (const float*)d_in[11];
    const float* Wo   = (const float*)d_in[12];
    const float* bo   = (const float*)d_in[13];
    float* out = (float*)d_out;

    const int B = in_sizes[0] / (SEQ * DIM);  // 16384
    mha_fused_kernel<<<B, NTHR>>>(Q, K, V, ln_g, ln_b,
                                  Wq, bq, Wk, bk, Wv, bv, Wo, bo, out);
}

// round 4
// speedup vs baseline: 2.1155x; 1.1380x over previous
#include <cuda_runtime.h>
#include <math.h>

#define SEQ 50
#define DIM 32
#define NTHR 256
#define NWARP 8
#define FULLM 0xffffffffu
#define WPITCH 33

// Folded weights, shared by all batches (computed once by prep_kernel)
__device__ float gWfold[3 * DIM * DIM];   // rows pre-scaled by ln_g
__device__ float gB2[3 * DIM];            // bias + b . W^T
__device__ float gSw[3 * DIM];            // rowsum of g-scaled W

__global__ void prep_kernel(
    const float* __restrict__ ln_g, const float* __restrict__ ln_b,
    const float* __restrict__ Wq, const float* __restrict__ bq,
    const float* __restrict__ Wk, const float* __restrict__ bk,
    const float* __restrict__ Wv, const float* __restrict__ bv)
{
    int j = threadIdx.x;
    if (j >= 3 * DIM) return;
    int t = j >> 5, r = j & 31;
    const float* W    = (t == 0) ? Wq : (t == 1) ? Wk : Wv;
    const float* bias = (t == 0) ? bq : (t == 1) ? bk : bv;
    float b2 = bias[r], sw = 0.f;
    #pragma unroll
    for (int d = 0; d < DIM; d++) {
        float w  = W[r * DIM + d];
        float gw = w * ln_g[d];
        b2 = fmaf(w, ln_b[d], b2);
        sw += gw;
        gWfold[(t * DIM + r) * DIM + d] = gw;
    }
    gB2[j] = b2;
    gSw[j] = sw;
}

__global__ __launch_bounds__(NTHR, 4) void mha_fused_kernel(
    const float* __restrict__ Q, const float* __restrict__ K, const float* __restrict__ V,
    const float* __restrict__ Wo, const float* __restrict__ bo,
    float* __restrict__ out)
{
    __shared__ __align__(16) float sbuf[3 * SEQ * DIM];  // raw rows -> projected in place; q -> ctx
    __shared__ float sW[4 * DIM * WPITCH];               // folded Wq,Wk,Wv + raw Wo, pitch 33
    __shared__ float2 sStats[3 * SEQ];                   // (mu, inv) per row
    __shared__ float sB2[3 * DIM], sSw[3 * DIM], sbo[DIM];

    const int tid  = threadIdx.x;
    const int lane = tid & 31;
    const int wid  = tid >> 5;
    const size_t boff = (size_t)blockIdx.x * (SEQ * DIM);
    const float* Qb = Q + boff;
    const float* Kb = K + boff;
    const float* Vb = V + boff;

    // ---- stage weights (folded qkv from global, Wo raw) into padded smem ----
    for (int i = tid; i < 4 * DIM * DIM; i += NTHR) {
        int t = i >> 10, idx = i & 1023;
        int r = idx >> 5, c = idx & 31;
        float v = (t < 3) ? gWfold[i] : Wo[idx];
        sW[t * DIM * WPITCH + r * WPITCH + c] = v;
    }
    if (tid < 3 * DIM) { sB2[tid] = gB2[tid]; sSw[tid] = gSw[tid]; }
    if (tid < DIM) sbo[tid] = bo[tid];

    // ---- raw row loads + LN stats (sum x, sum x^2), 4 rows per warp-iter ----
    {
        const int rsub = lane >> 3;
        const int rk   = lane & 7;
        for (int blk = wid; blk < (3 * SEQ + 3) / 4; blk += NWARP) {
            int gr = blk * 4 + rsub;
            float4 xv = make_float4(0.f, 0.f, 0.f, 0.f);
            if (gr < 3 * SEQ) {
                int t = gr / SEQ;
                int r = gr - t * SEQ;
                const float* src = (t == 0) ? Qb : (t == 1) ? Kb : Vb;
                xv = *(const float4*)(src + r * DIM + rk * 4);
                *(float4*)(sbuf + gr * DIM + rk * 4) = xv;
            }
            float s1 = xv.x + xv.y + xv.z + xv.w;
            float s2 = xv.x * xv.x + xv.y * xv.y + xv.z * xv.z + xv.w * xv.w;
            #pragma unroll
            for (int o = 4; o; o >>= 1) {
                s1 += __shfl_xor_sync(FULLM, s1, o);
                s2 += __shfl_xor_sync(FULLM, s2, o);
            }
            if (rk == 0 && gr < 3 * SEQ) {
                float mu  = s1 * (1.0f / DIM);
                float var = s2 * (1.0f / DIM) - mu * mu;
                sStats[gr] = make_float2(mu, rsqrtf(var + 1e-5f));
            }
        }
    }
    __syncthreads();

    // ---- projections: out[s][j] = inv_s*(dot(x_s, W'_j) - mu_s*sw_j) + b2_j
    // warp w handles tasks 3w..3w+2 (task = t*8 + chunk); wreg reloaded on t change
    {
        float wreg[DIM];
        float b2 = 0.f, swv = 0.f;
        int tprev = -1;
        #pragma unroll
        for (int k = 0; k < 3; k++) {
            const int task = wid * 3 + k;
            const int t = task >> 3;
            const int c = task & 7;
            if (t != tprev) {
                const float* wr = sW + (t * DIM + lane) * WPITCH;
                #pragma unroll
                for (int d = 0; d < DIM; d++) wreg[d] = wr[d];
                b2  = sB2[t * DIM + lane];
                swv = sSw[t * DIM + lane];
                tprev = t;
            }
            const int r0 = (c * SEQ) >> 3;
            const int r1 = ((c + 1) * SEQ) >> 3;
            float* base = sbuf + t * SEQ * DIM;
            float orow[7];
            const int nr = r1 - r0;
            #pragma unroll
            for (int r = 0; r < 7; r++) {
                if (r < nr) {
                    const float4* xr = (const float4*)(base + (r0 + r) * DIM);
                    float dot = 0.f;
                    #pragma unroll
                    for (int k2 = 0; k2 < 8; k2++) {
                        float4 xv = xr[k2];
                        dot = fmaf(xv.x, wreg[k2 * 4 + 0],
                              fmaf(xv.y, wreg[k2 * 4 + 1],
                              fmaf(xv.z, wreg[k2 * 4 + 2],
                              fmaf(xv.w, wreg[k2 * 4 + 3], dot))));
                    }
                    float2 st = sStats[t * SEQ + r0 + r];
                    orow[r] = fmaf(st.y, fmaf(-st.x, swv, dot), b2);
                }
            }
            __syncwarp();
            #pragma unroll
            for (int r = 0; r < 7; r++)
                if (r < nr) base[(r0 + r) * DIM + lane] = orow[r];
        }
    }
    __syncthreads();

    // ---- paired causal attention: thread = (head, pair p), queries i1=p, i2=49-p ----
    if (tid < 4 * (SEQ / 2)) {
        const int h = tid & 3;
        const int p = tid >> 2;           // 0..24
        const int i2 = SEQ - 1 - p;       // 25..49
        const float* sk_ = sbuf + SEQ * DIM;
        const float* sv_ = sbuf + 2 * SEQ * DIM;
        const float scale = 0.35355339059327373f;  // 1/sqrt(8)

        const float* q1p = sbuf + p  * DIM + h * 8;
        const float* q2p = sbuf + i2 * DIM + h * 8;
        float4 q1a = *(const float4*)q1p, q1b = *(const float4*)(q1p + 4);
        float4 q2a = *(const float4*)q2p, q2b = *(const float4*)(q2p + 4);
        q1a.x *= scale; q1a.y *= scale; q1a.z *= scale; q1a.w *= scale;
        q1b.x *= scale; q1b.y *= scale; q1b.z *= scale; q1b.w *= scale;
        q2a.x *= scale; q2a.y *= scale; q2a.z *= scale; q2a.w *= scale;
        q2b.x *= scale; q2b.y *= scale; q2b.z *= scale; q2b.w *= scale;

        float ssum1 = 0.f, ssum2 = 0.f;
        float4 a1a = make_float4(0.f,0.f,0.f,0.f), a1b = make_float4(0.f,0.f,0.f,0.f);
        float4 a2a = make_float4(0.f,0.f,0.f,0.f), a2b = make_float4(0.f,0.f,0.f,0.f);

        for (int j = 0; j <= i2; j++) {
            const float* kr = sk_ + j * DIM + h * 8;
            float4 k0 = *(const float4*)kr;
            float4 k1 = *(const float4*)(kr + 4);
            const float* vr = sv_ + j * DIM + h * 8;
            float4 v0 = *(const float4*)vr;
            float4 v1 = *(const float4*)(vr + 4);

            float d2 = q2a.x*k0.x + q2a.y*k0.y + q2a.z*k0.z + q2a.w*k0.w
                     + q2b.x*k1.x + q2b.y*k1.y + q2b.z*k1.z + q2b.w*k1.w;
            float w2 = __expf(d2);
            ssum2 += w2;
            a2a.x = fmaf(w2, v0.x, a2a.x); a2a.y = fmaf(w2, v0.y, a2a.y);
            a2a.z = fmaf(w2, v0.z, a2a.z); a2a.w = fmaf(w2, v0.w, a2a.w);
            a2b.x = fmaf(w2, v1.x, a2b.x); a2b.y = fmaf(w2, v1.y, a2b.y);
            a2b.z = fmaf(w2, v1.z, a2b.z); a2b.w = fmaf(w2, v1.w, a2b.w);

            if (j <= p) {
                float d1 = q1a.x*k0.x + q1a.y*k0.y + q1a.z*k0.z + q1a.w*k0.w
                         + q1b.x*k1.x + q1b.y*k1.y + q1b.z*k1.z + q1b.w*k1.w;
                float w1 = __expf(d1);
                ssum1 += w1;
                a1a.x = fmaf(w1, v0.x, a1a.x); a1a.y = fmaf(w1, v0.y, a1a.y);
                a1a.z = fmaf(w1, v0.z, a1a.z); a1a.w = fmaf(w1, v0.w, a1a.w);
                a1b.x = fmaf(w1, v1.x, a1b.x); a1b.y = fmaf(w1, v1.y, a1b.y);
                a1b.z = fmaf(w1, v1.z, a1b.z); a1b.w = fmaf(w1, v1.w, a1b.w);
            }
        }
        float inv1 = 1.0f / ssum1;
        float inv2 = 1.0f / ssum2;
        a1a.x *= inv1; a1a.y *= inv1; a1a.z *= inv1; a1a.w *= inv1;
        a1b.x *= inv1; a1b.y *= inv1; a1b.z *= inv1; a1b.w *= inv1;
        a2a.x *= inv2; a2a.y *= inv2; a2a.z *= inv2; a2a.w *= inv2;
        a2b.x *= inv2; a2b.y *= inv2; a2b.z *= inv2; a2b.w *= inv2;

        float* c1 = sbuf + p  * DIM + h * 8;
        float* c2 = sbuf + i2 * DIM + h * 8;
        *(float4*)c1 = a1a; *(float4*)(c1 + 4) = a1b;
        *(float4*)c2 = a2a; *(float4*)(c2 + 4) = a2b;
    }
    __syncthreads();

    // ---- output projection + residual (Wo register-resident) ----
    {
        const float* wr = sW + (3 * DIM + lane) * WPITCH;
        float wreg[DIM];
        #pragma unroll
        for (int d = 0; d < DIM; d++) wreg[d] = wr[d];
        const float b2 = sbo[lane];
        float* ob = out + boff;
        const int r0 = (wid * SEQ) >> 3;
        const int r1 = ((wid + 1) * SEQ) >> 3;
        for (int r = r0; r < r1; r++) {
            const float4* xr = (const float4*)(sbuf + r * DIM);
            float dot = b2;
            #pragma unroll
            for (int k2 = 0; k2 < 8; k2++) {
                float4 xv = xr[k2];
                dot = fmaf(xv.x, wreg[k2 * 4 + 0],
                      fmaf(xv.y, wreg[k2 * 4 + 1],
                      fmaf(xv.z, wreg[k2 * 4 + 2],
                      fmaf(xv.w, wreg[k2 * 4 + 3], dot))));
            }
            ob[r * DIM + lane] = dot + Qb[r * DIM + lane];
        }
    }
}

extern "C" void kernel_launch(void* const* d_in, const int* in_sizes, int n_in,
                              void* d_out, int out_size) {
    const float* Q    = (const float*)d_in[0];
    const float* K    = (const float*)d_in[1];
    const float* V    = (const float*)d_in[2];
    // d_in[3] = mask (static causal triu, implemented analytically)
    const float* ln_g = (const float*)d_in[4];
    const float* ln_b = (const float*)d_in[5];
    const float* Wq   = (const float*)d_in[6];
    const float* bq   = (const float*)d_in[7];
    const float* Wk   = (const float*)d_in[8];
    const float* bk   = (const float*)d_in[9];
    const float* Wv   = (const float*)d_in[10];
    const float* bv   = (const float*)d_in[11];
    const float* Wo   = (const float*)d_in[12];
    const float* bo   = (const float*)d_in[13];
    float* out = (float*)d_out;

    const int B = in_sizes[0] / (SEQ * DIM);  // 16384
    prep_kernel<<<1, 96>>>(ln_g, ln_b, Wq, bq, Wk, bk, Wv, bv);
    mha_fused_kernel<<<B, NTHR>>>(Q, K, V, Wo, bo, out);
}